// round 1
// baseline (speedup 1.0000x reference)
#include <cuda_runtime.h>

#define HH 384
#define WW 384
#define BB 8
#define CC 4
#define NPIX (HH*WW)        // 147456
#define NINST (BB*CC)       // 32
#define BIGF 1e8f
#define NBLK3 4608          // (BB*NPIX)/256 exactly

// Scratch: d1[pol][b][c][h][w]  (row-pass squared horizontal distances)
__device__ float g_d1[2u * NINST * NPIX];   // ~37.75 MB
__device__ int   g_cnt[NINST];
__device__ float g_part[NBLK3];

// ---------------------------------------------------------------------------
__global__ void k_zero_cnt() {
    if (threadIdx.x < NINST) g_cnt[threadIdx.x] = 0;
}

// ---------------------------------------------------------------------------
// nearest set-bit squared distance in a 384-bit row (12 words), optionally on
// the complement. Returns BIGF if no set bit (matches reference: min_y BIG+(x-y)^2 = BIG at y=x).
__device__ __forceinline__ float nearest_sq(const unsigned* __restrict__ words, int x, bool inv) {
    int w0 = x >> 5, b0 = x & 31;
    unsigned wv = words[w0]; if (inv) wv = ~wv;

    int dl = 1 << 29;
    unsigned curl = wv & (0xFFFFFFFFu >> (31 - b0));   // bits 0..b0
    int wl = w0;
    while (curl == 0 && wl > 0) {
        --wl;
        unsigned t = words[wl]; if (inv) t = ~t;
        curl = t;
    }
    if (curl) dl = x - (wl * 32 + (31 - __clz(curl)));

    int dr = 1 << 29;
    unsigned curr = wv & (0xFFFFFFFFu << b0);          // bits b0..31
    int wr = w0;
    while (curr == 0 && wr < 11) {
        ++wr;
        unsigned t = words[wr]; if (inv) t = ~t;
        curr = t;
    }
    if (curr) dr = (wr * 32 + (__ffs(curr) - 1)) - x;

    int d = min(dl, dr);
    if (d >= (1 << 28)) return BIGF;
    float fd = (float)d;
    return fd * fd;
}

// Row pass: one block per (b,h) row; 384 threads. Ballot-based bitmasks per
// class, exact nearest-bit distances, coalesced d1 writes, class counts.
__global__ void k_rowpass(const int* __restrict__ targets) {
    __shared__ unsigned mEq[CC][12];
    __shared__ int scnt[CC];

    int b = blockIdx.x / HH;
    int h = blockIdx.x % HH;
    int x = threadIdx.x;          // 0..383
    int warp = x >> 5, lane = x & 31;

    if (x < CC) scnt[x] = 0;
    __syncthreads();

    int t = targets[(b * HH + h) * WW + x];

#pragma unroll
    for (int c = 0; c < CC; ++c) {
        unsigned m = __ballot_sync(0xFFFFFFFFu, t == c);
        if (lane == 0) {
            mEq[c][warp] = m;
            atomicAdd(&scnt[c], __popc(m));
        }
    }
    __syncthreads();

    if (x < CC) atomicAdd(&g_cnt[b * CC + x], scnt[x]);

#pragma unroll
    for (int c = 0; c < CC; ++c) {
        float deq = nearest_sq(mEq[c], x, false);
        float dne = nearest_sq(mEq[c], x, true);
        int inst = b * CC + c;
        g_d1[((unsigned)(0 * NINST + inst) * NPIX) + h * WW + x] = deq;
        g_d1[((unsigned)(1 * NINST + inst) * NPIX) + h * WW + x] = dne;
    }
}

// ---------------------------------------------------------------------------
// Exact vertical min-plus with early exit: once dh^2 >= best, all remaining
// candidates are >= dh^2 >= best. All finite arithmetic exact in fp32.
__device__ __forceinline__ float ringmin(const float* __restrict__ p, int h, int w) {
    float best = __ldg(p + h * WW + w);
    float q = 1.0f, step = 3.0f;   // q = dh^2, next increment 2*dh+1
#pragma unroll 1
    for (int dh = 1; dh < HH; ++dh) {
        if (q >= best) break;
        int hm = h - dh, hp = h + dh;
        if (hm >= 0) best = fminf(best, __ldg(p + hm * WW + w) + q);
        if (hp < HH) best = fminf(best, __ldg(p + hp * WW + w) + q);
        q += step; step += 2.0f;
    }
    return best;
}

// Fused: col pass (both polarities, 4 classes) + phi + softmax + weighted sum,
// block partial to fixed slot (deterministic).
__global__ void __launch_bounds__(256) k_loss(const float* __restrict__ logits) {
    int pid = blockIdx.x * 256 + threadIdx.x;     // 0 .. BB*NPIX-1 (exact)
    int b = pid / NPIX;
    int r = pid - b * NPIX;
    int h = r / WW;
    int w = r - h * WW;

    float l0 = logits[(b * CC + 0) * NPIX + r];
    float l1 = logits[(b * CC + 1) * NPIX + r];
    float l2 = logits[(b * CC + 2) * NPIX + r];
    float l3 = logits[(b * CC + 3) * NPIX + r];
    float m = fmaxf(fmaxf(l0, l1), fmaxf(l2, l3));
    float e0 = expf(l0 - m), e1 = expf(l1 - m), e2 = expf(l2 - m), e3 = expf(l3 - m);
    float inv = 1.0f / (e0 + e1 + e2 + e3);
    float pr[4] = { e0 * inv, e1 * inv, e2 * inv, e3 * inv };

    float acc = 0.0f;
#pragma unroll 1
    for (int c = 0; c < CC; ++c) {
        int inst = b * CC + c;
        const float* pp = g_d1 + (unsigned)(0 * NINST + inst) * NPIX;
        const float* pn = g_d1 + (unsigned)(1 * NINST + inst) * NPIX;
        float pos2 = ringmin(pp, h, w);
        float neg2 = ringmin(pn, h, w);
        int cnt = g_cnt[inst];
        float phi;
        if (cnt == 0)           phi = sqrtf(pos2);
        else if (cnt == NPIX)   phi = -sqrtf(neg2);
        else                    phi = sqrtf(pos2) - sqrtf(neg2) + 1.0f;
        acc += pr[c] * phi;
    }

    // block reduction (fixed shape -> deterministic)
    int lane = threadIdx.x & 31, wid = threadIdx.x >> 5;
#pragma unroll
    for (int o = 16; o; o >>= 1) acc += __shfl_down_sync(0xFFFFFFFFu, acc, o);
    __shared__ float sm[8];
    if (lane == 0) sm[wid] = acc;
    __syncthreads();
    if (threadIdx.x < 8) {
        float v = sm[threadIdx.x];
#pragma unroll
        for (int o = 4; o; o >>= 1) v += __shfl_down_sync(0x000000FFu, v, o);
        if (threadIdx.x == 0) g_part[blockIdx.x] = v;
    }
}

// ---------------------------------------------------------------------------
__global__ void k_final(float* __restrict__ out) {
    float s = 0.0f;
    for (int i = threadIdx.x; i < NBLK3; i += 256) s += g_part[i];
    int lane = threadIdx.x & 31, wid = threadIdx.x >> 5;
#pragma unroll
    for (int o = 16; o; o >>= 1) s += __shfl_down_sync(0xFFFFFFFFu, s, o);
    __shared__ float sm[8];
    if (lane == 0) sm[wid] = s;
    __syncthreads();
    if (threadIdx.x < 8) {
        float v = sm[threadIdx.x];
#pragma unroll
        for (int o = 4; o; o >>= 1) v += __shfl_down_sync(0x000000FFu, v, o);
        if (threadIdx.x == 0)
            out[0] = v * (1.0f / ((float)BB * CC * NPIX));
    }
}

// ---------------------------------------------------------------------------
extern "C" void kernel_launch(void* const* d_in, const int* in_sizes, int n_in,
                              void* d_out, int out_size) {
    const float* logits  = (const float*)d_in[0];
    const int*   targets = (const int*)d_in[1];
    float* out = (float*)d_out;

    k_zero_cnt<<<1, 32>>>();
    k_rowpass<<<BB * HH, 384>>>(targets);
    k_loss<<<NBLK3, 256>>>(logits);
    k_final<<<1, 256>>>(out);
}